// round 1
// baseline (speedup 1.0000x reference)
#include <cuda_runtime.h>

// Problem constants
#define N_CLS 64
#define K_SHOT 64
#define D_DIM 640
#define Q_PER 2048
#define NQ (N_CLS * Q_PER)        // 131072 query rows
#define SUP_ROWS (N_CLS * K_SHOT) // 4096 support rows

typedef unsigned long long ull;

// Transposed, normalized prototypes: g_Pt[d * 64 + n] = prototypes[n][d]
__device__ __align__(16) float g_Pt[D_DIM * N_CLS];

// ---------------- packed f32x2 helpers (sm_100+) ----------------
__device__ __forceinline__ ull pack2(float x, float y) {
    ull r;
    asm("mov.b64 %0, {%1, %2};" : "=l"(r) : "f"(x), "f"(y));
    return r;
}
__device__ __forceinline__ void unpack2(ull v, float &x, float &y) {
    asm("mov.b64 {%0, %1}, %2;" : "=f"(x), "=f"(y) : "l"(v));
}
__device__ __forceinline__ void ffma2(ull &d, ull a, ull b) {
    asm("fma.rn.f32x2 %0, %1, %2, %0;" : "+l"(d) : "l"(a), "l"(b));
}

// ======================================================================
// Kernel 1: per-class prototype computation. One block per class i.
//   pu[i][d]   = mean_k emb[(k*64 + i)*D + d]           (strided rows!)
//   num[j]     = dot(pu[i], row_j), row_j = emb[(i*64+j)*D]
//   dis[j]     = exp(num[j] / (max(||pu||,1e-8) * max(||row_j||,1e-8)))
//   w[j]       = dis[j] / sum_j dis
//   pd[d]      = sum_j w[j] * row_j[d]
//   Pt[d][i]   = pd[d] / max(||pd||, 1e-12)
// ======================================================================
__global__ void __launch_bounds__(256) proto_kernel(const float* __restrict__ emb) {
    const int i    = blockIdx.x;
    const int tid  = threadIdx.x;
    const int lane = tid & 31;
    const int wid  = tid >> 5;

    __shared__ float s_pu[D_DIM];
    __shared__ float s_w[64];
    __shared__ float s_red[8];
    __shared__ float s_pn, s_isum, s_inorm;

    // ---- proto_unnorm (strided mean) + its squared norm ----
    float pn2 = 0.f;
    for (int d = tid; d < D_DIM; d += 256) {
        float s = 0.f;
        #pragma unroll 8
        for (int k = 0; k < K_SHOT; ++k)
            s += emb[(size_t)(k * N_CLS + i) * D_DIM + d];
        s *= (1.0f / 64.0f);
        s_pu[d] = s;
        pn2 += s * s;
    }
    #pragma unroll
    for (int o = 16; o; o >>= 1) pn2 += __shfl_xor_sync(0xffffffffu, pn2, o);
    if (lane == 0) s_red[wid] = pn2;
    __syncthreads();
    if (tid == 0) {
        float t = 0.f;
        #pragma unroll
        for (int w = 0; w < 8; ++w) t += s_red[w];
        s_pn = fmaxf(sqrtf(t), 1e-8f);
    }
    __syncthreads();
    const float p_norm = s_pn;

    // ---- per-shot cosine-similarity dis[j] (one warp per j, round-robin) ----
    const float* blk = emb + (size_t)i * 64 * D_DIM;
    for (int j = wid; j < 64; j += 8) {
        const float* row = blk + (size_t)j * D_DIM;
        float dot = 0.f, s2 = 0.f;
        for (int d = lane; d < D_DIM; d += 32) {
            float a = row[d];
            dot += a * s_pu[d];
            s2  += a * a;
        }
        #pragma unroll
        for (int o = 16; o; o >>= 1) {
            dot += __shfl_xor_sync(0xffffffffu, dot, o);
            s2  += __shfl_xor_sync(0xffffffffu, s2, o);
        }
        if (lane == 0) {
            float sn = fmaxf(sqrtf(s2), 1e-8f);
            s_w[j] = expf(dot / (p_norm * sn));
        }
    }
    __syncthreads();

    // ---- softmax denominator (deterministic reduction) ----
    if (tid < 32) {
        float v = s_w[tid] + s_w[tid + 32];
        #pragma unroll
        for (int o = 16; o; o >>= 1) v += __shfl_xor_sync(0xffffffffu, v, o);
        if (tid == 0) s_isum = 1.0f / v;
    }
    __syncthreads();
    const float inv_sum = s_isum;

    // ---- weighted prototype + normalization ----
    float pd0 = 0.f, pd1 = 0.f, pd2 = 0.f;
    const int d0 = tid, d1 = tid + 256, d2 = tid + 512;  // d2 valid iff tid < 128
    for (int j = 0; j < 64; ++j) {
        float wj = s_w[j] * inv_sum;
        const float* row = blk + (size_t)j * D_DIM;
        pd0 += wj * row[d0];
        pd1 += wj * row[d1];
        if (d2 < D_DIM) pd2 += wj * row[d2];
    }
    float q2 = pd0 * pd0 + pd1 * pd1 + ((d2 < D_DIM) ? pd2 * pd2 : 0.f);
    #pragma unroll
    for (int o = 16; o; o >>= 1) q2 += __shfl_xor_sync(0xffffffffu, q2, o);
    __syncthreads();           // protect s_red reuse
    if (lane == 0) s_red[wid] = q2;
    __syncthreads();
    if (tid == 0) {
        float t = 0.f;
        #pragma unroll
        for (int w = 0; w < 8; ++w) t += s_red[w];
        s_inorm = 1.0f / fmaxf(sqrtf(t), 1e-12f);
    }
    __syncthreads();
    const float innorm = s_inorm;

    g_Pt[d0 * N_CLS + i] = pd0 * innorm;
    g_Pt[d1 * N_CLS + i] = pd1 * innorm;
    if (d2 < D_DIM) g_Pt[d2 * N_CLS + i] = pd2 * innorm;
}

// ======================================================================
// Kernel 2: logits = query @ P^T * (1/TAU)
//   M = 131072, C = 64, K = 640, fp32 via packed FFMA2 (fma.rn.f32x2).
//   Block: 256 threads, M-tile 256. Thread: 2 rows x 32 cols
//   (cg = tid&1 selects column half; rg = tid>>1 selects row pair).
//   P tile (32 k x 64 c) is a contiguous 8KB slab of g_Pt; loaded to smem,
//   read as LDS.64 directly into FFMA2 operand pairs (no pack MOVs for B).
// ======================================================================
__global__ void __launch_bounds__(256, 2) logits_kernel(const float* __restrict__ qry,
                                                        float* __restrict__ out) {
    __shared__ __align__(16) float sQ[256 * 33];   // pitch 33 -> conflict-free
    __shared__ __align__(16) float sP[32 * 64];

    const int tid = threadIdx.x;
    const int cg  = tid & 1;          // column half: cols [cg*32, cg*32+32)
    const int rg  = tid >> 1;         // row pair index 0..127
    const int rA  = rg * 2;
    const int rB  = rA + 1;
    const size_t rowBase = (size_t)blockIdx.x * 256;

    ull acc0[16], acc1[16];
    #pragma unroll
    for (int m = 0; m < 16; ++m) { acc0[m] = 0ull; acc1[m] = 0ull; }  // {+0.f,+0.f}

    for (int kk = 0; kk < D_DIM; kk += 32) {
        __syncthreads();
        // ---- stage Q tile: 256 rows x 32 k (coalesced float4 loads) ----
        #pragma unroll
        for (int jj = 0; jj < 8; ++jj) {
            int f4 = tid + jj * 256;           // 0..2047
            int r  = f4 >> 3;                  // row 0..255
            int kq = (f4 & 7) << 2;            // k offset 0,4,...,28
            float4 v = *(const float4*)(qry + (rowBase + r) * D_DIM + kk + kq);
            float* dst = &sQ[r * 33 + kq];
            dst[0] = v.x; dst[1] = v.y; dst[2] = v.z; dst[3] = v.w;
        }
        // ---- stage P tile: contiguous 8KB from g_Pt ----
        #pragma unroll
        for (int jj = 0; jj < 2; ++jj) {
            int f4 = tid + jj * 256;           // 0..511
            *(float4*)(sP + f4 * 4) = *(const float4*)(g_Pt + (size_t)kk * 64 + f4 * 4);
        }
        __syncthreads();

        // ---- FFMA2 mainloop ----
        #pragma unroll 4
        for (int kp = 0; kp < 32; ++kp) {
            float qa = sQ[rA * 33 + kp];
            float qb = sQ[rB * 33 + kp];
            ull qa2 = pack2(qa, qa);
            ull qb2 = pack2(qb, qb);
            const ull* pr = (const ull*)(sP + kp * 64 + cg * 32);  // 16 col-pairs
            #pragma unroll
            for (int m = 0; m < 16; ++m) {
                ull p = pr[m];                  // LDS.64 -> register pair
                ffma2(acc0[m], qa2, p);
                ffma2(acc1[m], qb2, p);
            }
        }
    }

    // ---- epilogue: scale by 1/TAU = 10 and store as float4 ----
    const float sc = 10.0f;
    #pragma unroll
    for (int m = 0; m < 8; ++m) {
        float x, y, z, w;
        unpack2(acc0[2 * m],     x, y);
        unpack2(acc0[2 * m + 1], z, w);
        *(float4*)(out + (rowBase + rA) * 64 + cg * 32 + 4 * m) =
            make_float4(x * sc, y * sc, z * sc, w * sc);
        unpack2(acc1[2 * m],     x, y);
        unpack2(acc1[2 * m + 1], z, w);
        *(float4*)(out + (rowBase + rB) * 64 + cg * 32 + 4 * m) =
            make_float4(x * sc, y * sc, z * sc, w * sc);
    }
}

// ======================================================================
extern "C" void kernel_launch(void* const* d_in, const int* in_sizes, int n_in,
                              void* d_out, int out_size) {
    const float* emb = (const float*)d_in[0];
    float* out = (float*)d_out;

    // Phase 1: prototypes (writes g_Pt) — one block per class
    proto_kernel<<<N_CLS, 256>>>(emb);

    // Phase 2: logits GEMM over the 131072 query rows
    const float* qry = emb + (size_t)SUP_ROWS * D_DIM;
    logits_kernel<<<NQ / 256, 256>>>(qry, out);
}